// round 15
// baseline (speedup 1.0000x reference)
#include <cuda_runtime.h>

#define FULLMASK 0xffffffffu
#define NEG2  (-1.4426950e9f)          // -1e9 in base-2 log domain
#define FLR   (1e-30f)
#define BIGNEG (-3.0e38f)
#define INVLN2 1.4426950408889634f
#define LN2    0.6931471805599453f

__device__ float g_beta[256 * 128 * 128 * 3];   // beta scratch (50.3 MB)

// base-2 logsumexp of 2
__device__ __forceinline__ float lse2b(float a, float b) {
    float mx = fmaxf(a, b);
    float mn = fminf(a, b);
    return mx + log2f(1.0f + exp2f(mn - mx));
}
__device__ __forceinline__ float fmax3(float a, float b, float c) {
    return fmaxf(fmaxf(a, b), c);
}
__device__ __forceinline__ void relstore(int* p, int v) {
    asm volatile("st.release.cta.b32 [%0], %1;" :: "l"(p), "r"(v) : "memory");
}
__device__ __forceinline__ int acqload(int* p) {
    int v; asm volatile("ld.acquire.cta.b32 %0, [%1];" : "=r"(v) : "l"(p) : "memory");
    return v;
}
// bounded pure spin, nanosleep only as cold-start fallback
__device__ __forceinline__ void waitflag(int* p) {
    if (acqload(p)) return;
    int tries = 0;
    while (!acqload(p)) { if (++tries > 64) __nanosleep(64); }
}

// One CTA (8 warps) per batch. Warps 0-3: forward alpha (cols 32s..32s+15+16,
// 1 col/lane, left->right mailbox chain) -> out (base-2 domain). Warps 4-7:
// beta lattice (independent), right->left chain -> g_beta (base-2). Softmax
// scan with row-tracked exp reference. Combine converts back with *ln2.
__global__ void __launch_bounds__(256, 1)
fb_kernel(const float* __restrict__ theta, const float* __restrict__ Aall,
          float* __restrict__ out)
{
    __shared__ float fm[3][128], fx[3][128], fy[3][128];   // fwd mailboxes
    __shared__ int   ff[3][128];
    __shared__ float bu0s[3][128], bu2s[3][128];           // beta mailboxes
    __shared__ int   bf[3][128];
    __shared__ float shlogZ;

    const int tid  = threadIdx.x;
    const int w    = tid >> 5;
    const int lane = tid & 31;
    const int b    = blockIdx.x;

    for (int j = tid; j < 3 * 128; j += 256) {
        (&ff[0][0])[j] = 0;
        (&bf[0][0])[j] = 0;
    }
    __syncthreads();

    const float* Ab = Aall + (size_t)b * 9;
    float As[9], E[9];
#pragma unroll
    for (int t = 0; t < 9; t++) { As[t] = Ab[t] * INVLN2; E[t] = exp2f(As[t]); }
    const float A02 = As[2], A12 = As[5], A20 = As[6], A21 = As[7], A22 = As[8];
    const float eM0 = E[0], eM1 = E[3], eM2 = E[6];   // exp(A[:,0]) linear
    const float eX0 = E[1], eX1 = E[4], eX2 = E[7];   // exp(A[:,1]) linear

    const size_t base_off = (size_t)b * 49152;
    const float* th = theta + base_off;
    float* po = out + base_off;
    float* pb = g_beta + base_off;

    if (w < 4) {
        // ====================== FORWARD (alpha, base-2) ======================
        const int s = w;
        const int col = s * 32 + lane;
        const int off = col * 3;
        float pm = NEG2, px = NEG2, py = NEG2;
        float dM = NEG2, dX = NEG2, dY = NEG2;   // mailbox row i-1 triple (regs)
        float la0 = NEG2, la1 = NEG2, la2 = NEG2;
        float Rest = BIGNEG;

        float t0 = th[off] * INVLN2, t1 = th[off + 1] * INVLN2, t2 = th[off + 2] * INVLN2;
        for (int i = 0; i < 128; i++) {
            float n0, n1, n2;
            if (i < 127) {
                int r = (i + 1) * 384 + off;
                n0 = th[r]; n1 = th[r + 1]; n2 = th[r + 2];
            }

            // ---- S prefix-sum (theta-only) ----
            float d = t2 + A22;
            float S = d;
#pragma unroll
            for (int o = 1; o < 32; o <<= 1) {
                float tS = __shfl_up_sync(FULLMASK, S, o);
                if (lane >= o) S += tS;
            }

            // ---- shared-exp of own prev-row triple; v-fold handoff ----
            float r0 = fmax3(pm, px, py);
            float Em = exp2f(pm - r0), Ex = exp2f(px - r0), Ey = exp2f(py - r0);
            float dotM = fmaf(eM0, Em, fmaf(eM1, Ex, fmaf(eM2, Ey, FLR)));
            float dotX = fmaf(eX0, Em, fmaf(eX1, Ex, fmaf(eX2, Ey, FLR)));
            float v = r0 + log2f(dotM);              // lse3 my right neighbor needs
            float x = t1 + r0 + log2f(dotX);

            float vsh = __shfl_up_sync(FULLMASK, v, 1);
            if (lane == 0) {
                if (s == 0) vsh = NEG2;
                else {
                    float rr = fmax3(dM, dX, dY);
                    float a0 = exp2f(dM - rr), a1 = exp2f(dX - rr), a2 = exp2f(dY - rr);
                    vsh = rr + log2f(fmaf(eM0, a0, fmaf(eM1, a1, fmaf(eM2, a2, FLR))));
                }
                if (s == 0 && i == 0) vsh = 0.0f;    // start cell (0,0,match)
            }
            float m = t0 + vsh;

            float mnb = __shfl_up_sync(FULLMASK, m, 1);
            float xnb = __shfl_up_sync(FULLMASK, x, 1);
            float c = t2 + lse2b(mnb + A02, xnb + A12);   // lane0 garbage (excluded)

            float e = c - S;
            if (Rest < -1.0e8f) {                 // cold segment: exact max
                float em = (lane == 0) ? BIGNEG : e;
#pragma unroll
                for (int o = 16; o > 0; o >>= 1)
                    em = fmaxf(em, __shfl_xor_sync(FULLMASK, em, o));
                Rest = em;
            }
            float Ee = (lane == 0) ? 0.0f : exp2f(fminf(e - Rest, 122.0f));
            float ss = Ee;                        // prefix sum of exps
#pragma unroll
            for (int o = 1; o < 32; o <<= 1) {
                float tS = __shfl_up_sync(FULLMASK, ss, o);
                if (lane >= o) ss += tS;
            }
            float bseP = Rest + log2f(ss + FLR);
            float bse = (lane == 0) ? NEG2 : bseP;
            Rest = __shfl_sync(FULLMASK, bseP, 31);   // track for next row

            // ---------- LATE (needs mailbox slot i) ----------
            float hm = NEG2, hx = NEG2, hy = NEG2;
            if (s > 0) {
                waitflag(&ff[s - 1][i]);
                hm = fm[s - 1][i]; hx = fx[s - 1][i]; hy = fy[s - 1][i];
            }
            float q0  = lse2b(hm + A02, hx + A12);
            float aux = lse2b(q0 - A22, hy);          // t2b cancels exactly
            float y = S + lse2b(bse, aux);

            int wo = i * 384 + off;
            po[wo] = m; po[wo + 1] = x; po[wo + 2] = y;

            if (s < 3 && lane == 31) {
                fm[s][i] = m; fx[s][i] = x; fy[s][i] = y;
                relstore(&ff[s][i], 1);
            }
            if (i == 127) { la0 = m; la1 = x; la2 = y; }

            pm = m; px = x; py = y;
            dM = hm; dX = hx; dY = hy;
            if (i < 127) { t0 = n0 * INVLN2; t1 = n1 * INVLN2; t2 = n2 * INVLN2; }
        }
        if (s == 3) {   // logZ (base-2) from alpha(127,127,:) held in lane 31
            la0 = __shfl_sync(FULLMASK, la0, 31);
            la1 = __shfl_sync(FULLMASK, la1, 31);
            la2 = __shfl_sync(FULLMASK, la2, 31);
            float r = fmax3(la0, la1, la2);
            float lz = r + log2f(exp2f(la0 - r) + exp2f(la1 - r) + exp2f(la2 - r));
            if (lane == 31) shlogZ = lz;
        }
    } else {
        // ====================== BETA (independent lattice, base-2) ==========
        const int wl = w - 4;                 // 0..3
        const int v = 3 - wl;                 // v=0 is the rightmost (producer) seg
        const int col = 32 * wl + 31 - lane;  // scan pos p = 32v+lane -> col 127-p
        const int off = col * 3;
        float u0p = NEG2, u1p = NEG2;
        float u0ext = NEG2;                   // bu0s[v-1][i+1], carried in a reg
        float Rest = BIGNEG;

        float t0 = th[127 * 384 + off] * INVLN2;
        float t1 = th[127 * 384 + off + 1] * INVLN2;
        float t2 = th[127 * 384 + off + 2] * INVLN2;
        for (int i = 127; i >= 0; i--) {
            float n0, n1, n2;
            if (i > 0) {
                int r = (i - 1) * 384 + off;
                n0 = th[r]; n1 = th[r + 1]; n2 = th[r + 2];
            }

            const bool lastcell = (v == 0 && lane == 0 && i == 127);

            // ---- S prefix-sum (theta-only) ----
            float d = t2 + A22;
            if (lastcell) d = 0.0f;
            float S = d;
#pragma unroll
            for (int o = 1; o < 32; o <<= 1) {
                float tS = __shfl_up_sync(FULLMASK, S, o);
                if (lane >= o) S += tS;
            }

            float u0n = __shfl_up_sync(FULLMASK, u0p, 1);
            if (lane == 0) u0n = u0ext;       // v==0: stays NEG2

            float c = t2 + lse2b(A20 + u0n, A21 + u1p);
            if (lastcell) c = t2;             // beta(127,127)=0

            float e = c - S;
            if (Rest < -1.0e8f) {             // cold segment: exact max
                float em = e;
#pragma unroll
                for (int o = 16; o > 0; o >>= 1)
                    em = fmaxf(em, __shfl_xor_sync(FULLMASK, em, o));
                Rest = em;
            }
            float Ee = exp2f(fminf(e - Rest, 122.0f));
            float ss = Ee;
#pragma unroll
            for (int o = 1; o < 32; o <<= 1) {
                float tS = __shfl_up_sync(FULLMASK, ss, o);
                if (lane >= o) ss += tS;
            }
            float bse = Rest + log2f(ss + FLR);
            Rest = __shfl_sync(FULLMASK, bse, 31);

            // ---------- LATE ----------
            float seed = NEG2, nexu0 = NEG2;
            if (v > 0) {
                waitflag(&bf[v - 1][i]);
                seed  = bu2s[v - 1][i];
                nexu0 = bu0s[v - 1][i];       // becomes u0ext for row i-1
            }
            float y = S + lse2b(bse, seed);   // inclusive u2 at this column
            float wr = __shfl_up_sync(FULLMASK, y, 1);
            if (lane == 0) wr = seed;         // exclusive (u2 at col j+1)

            float rr = fmax3(u0n, u1p, wr);
            float e0 = exp2f(u0n - rr), e1 = exp2f(u1p - rr), e2 = exp2f(wr - rr);
            float bb0 = rr + log2f(fmaf(E[0], e0, fmaf(E[1], e1, fmaf(E[2], e2, FLR))));
            float bb1 = rr + log2f(fmaf(E[3], e0, fmaf(E[4], e1, fmaf(E[5], e2, FLR))));
            float bb2 = rr + log2f(fmaf(E[6], e0, fmaf(E[7], e1, fmaf(E[8], e2, FLR))));
            if (lastcell) { bb0 = 0.f; bb1 = 0.f; bb2 = 0.f; }

            int ro = i * 384 + off;
            pb[ro] = bb0; pb[ro + 1] = bb1; pb[ro + 2] = bb2;

            float nu0 = bb0 + t0;
            float nu1 = bb1 + t1;

            if (v < 3 && lane == 31) {
                bu0s[v][i] = nu0;
                bu2s[v][i] = y;
                relstore(&bf[v][i], 1);
            }
            u0p = nu0; u1p = nu1; u0ext = nexu0;
            if (i > 0) { t0 = n0 * INVLN2; t1 = n1 * INVLN2; t2 = n2 * INVLN2; }
        }
    }

    // ====================== COMBINE (convert back with *ln2) ================
    __syncthreads();
    const float lz = shlogZ;
    const float4* bp4 = reinterpret_cast<const float4*>(pb);
    float4* op4 = reinterpret_cast<float4*>(po);
#pragma unroll 4
    for (int t = tid; t < 12288; t += 256) {
        float4 a = op4[t];
        float4 bb = bp4[t];
        op4[t] = make_float4((a.x + bb.x - lz) * LN2, (a.y + bb.y - lz) * LN2,
                             (a.z + bb.z - lz) * LN2, (a.w + bb.w - lz) * LN2);
    }
}

extern "C" void kernel_launch(void* const* d_in, const int* in_sizes, int n_in,
                              void* d_out, int out_size)
{
    const float* theta = (const float*)d_in[0];
    const float* A     = (const float*)d_in[1];
    float* out         = (float*)d_out;
    int B = in_sizes[1] / 9;   // 256
    fb_kernel<<<B, 256>>>(theta, A, out);
}

// round 16
// speedup vs baseline: 1.5907x; 1.5907x over previous
#include <cuda_runtime.h>

#define FULLMASK 0xffffffffu
#define NEG2  (-1.4426950e9f)          // -1e9 in base-2 log domain
#define FLR   (1e-30f)
#define BIGNEG (-3.0e38f)
#define INVLN2 1.4426950408889634f
#define LN2    0.6931471805599453f

__device__ float g_beta[256 * 128 * 128 * 3];   // beta scratch (50.3 MB)

// single-MUFU base-2 exp/log (approx, ftz) — NOT the slow accurate-path exp2f/log2f
__device__ __forceinline__ float ex2(float x) {
    float r; asm("ex2.approx.ftz.f32 %0, %1;" : "=f"(r) : "f"(x)); return r;
}
__device__ __forceinline__ float lg2(float x) {
    float r; asm("lg2.approx.ftz.f32 %0, %1;" : "=f"(r) : "f"(x)); return r;
}
// base-2 logsumexp of 2
__device__ __forceinline__ float lse2b(float a, float b) {
    float mx = fmaxf(a, b);
    float mn = fminf(a, b);
    return mx + lg2(1.0f + ex2(mn - mx));
}
__device__ __forceinline__ float fmax3(float a, float b, float c) {
    return fmaxf(fmaxf(a, b), c);
}
__device__ __forceinline__ void relstore(int* p, int v) {
    asm volatile("st.release.cta.b32 [%0], %1;" :: "l"(p), "r"(v) : "memory");
}
__device__ __forceinline__ int acqload(int* p) {
    int v; asm volatile("ld.acquire.cta.b32 %0, [%1];" : "=r"(v) : "l"(p) : "memory");
    return v;
}
// bounded pure spin, nanosleep only as cold-start fallback
__device__ __forceinline__ void waitflag(int* p) {
    if (acqload(p)) return;
    int tries = 0;
    while (!acqload(p)) { if (++tries > 64) __nanosleep(64); }
}

// One CTA (8 warps) per batch. Warps 0-3: forward alpha (cols 32s..32s+31,
// 1 col/lane, left->right mailbox chain) -> out (base-2 domain). Warps 4-7:
// beta lattice (independent), right->left chain -> g_beta (base-2). Softmax
// scan with row-tracked exp reference. Combine converts back with *ln2.
__global__ void __launch_bounds__(256, 1)
fb_kernel(const float* __restrict__ theta, const float* __restrict__ Aall,
          float* __restrict__ out)
{
    __shared__ float fm[3][128], fx[3][128], fy[3][128];   // fwd mailboxes
    __shared__ int   ff[3][128];
    __shared__ float bu0s[3][128], bu2s[3][128];           // beta mailboxes
    __shared__ int   bf[3][128];
    __shared__ float shlogZ;

    const int tid  = threadIdx.x;
    const int w    = tid >> 5;
    const int lane = tid & 31;
    const int b    = blockIdx.x;

    for (int j = tid; j < 3 * 128; j += 256) {
        (&ff[0][0])[j] = 0;
        (&bf[0][0])[j] = 0;
    }
    __syncthreads();

    const float* Ab = Aall + (size_t)b * 9;
    float As[9], E[9];
#pragma unroll
    for (int t = 0; t < 9; t++) { As[t] = Ab[t] * INVLN2; E[t] = ex2(As[t]); }
    const float A02 = As[2], A12 = As[5], A20 = As[6], A21 = As[7], A22 = As[8];
    const float eM0 = E[0], eM1 = E[3], eM2 = E[6];   // exp(A[:,0]) linear
    const float eX0 = E[1], eX1 = E[4], eX2 = E[7];   // exp(A[:,1]) linear

    const size_t base_off = (size_t)b * 49152;
    const float* th = theta + base_off;
    float* po = out + base_off;
    float* pb = g_beta + base_off;

    if (w < 4) {
        // ====================== FORWARD (alpha, base-2) ======================
        const int s = w;
        const int col = s * 32 + lane;
        const int off = col * 3;
        float pm = NEG2, px = NEG2, py = NEG2;
        float dM = NEG2, dX = NEG2, dY = NEG2;   // mailbox row i-1 triple (regs)
        float la0 = NEG2, la1 = NEG2, la2 = NEG2;
        float Rest = BIGNEG;

        float t0 = th[off] * INVLN2, t1 = th[off + 1] * INVLN2, t2 = th[off + 2] * INVLN2;
        for (int i = 0; i < 128; i++) {
            float n0, n1, n2;
            if (i < 127) {
                int r = (i + 1) * 384 + off;
                n0 = th[r]; n1 = th[r + 1]; n2 = th[r + 2];
            }

            // ---- S prefix-sum (theta-only) ----
            float d = t2 + A22;
            float S = d;
#pragma unroll
            for (int o = 1; o < 32; o <<= 1) {
                float tS = __shfl_up_sync(FULLMASK, S, o);
                if (lane >= o) S += tS;
            }

            // ---- shared-exp of own prev-row triple; v-fold handoff ----
            float r0 = fmax3(pm, px, py);
            float Em = ex2(pm - r0), Ex = ex2(px - r0), Ey = ex2(py - r0);
            float dotM = fmaf(eM0, Em, fmaf(eM1, Ex, fmaf(eM2, Ey, FLR)));
            float dotX = fmaf(eX0, Em, fmaf(eX1, Ex, fmaf(eX2, Ey, FLR)));
            float v = r0 + lg2(dotM);                // lse3 my right neighbor needs
            float x = t1 + r0 + lg2(dotX);

            float vsh = __shfl_up_sync(FULLMASK, v, 1);
            if (lane == 0) {
                if (s == 0) vsh = NEG2;
                else {
                    float rr = fmax3(dM, dX, dY);
                    float a0 = ex2(dM - rr), a1 = ex2(dX - rr), a2 = ex2(dY - rr);
                    vsh = rr + lg2(fmaf(eM0, a0, fmaf(eM1, a1, fmaf(eM2, a2, FLR))));
                }
                if (s == 0 && i == 0) vsh = 0.0f;    // start cell (0,0,match)
            }
            float m = t0 + vsh;

            float mnb = __shfl_up_sync(FULLMASK, m, 1);
            float xnb = __shfl_up_sync(FULLMASK, x, 1);
            float c = t2 + lse2b(mnb + A02, xnb + A12);   // lane0 garbage (excluded)

            float e = c - S;
            if (Rest < -1.0e8f) {                 // cold segment: exact max
                float em = (lane == 0) ? BIGNEG : e;
#pragma unroll
                for (int o = 16; o > 0; o >>= 1)
                    em = fmaxf(em, __shfl_xor_sync(FULLMASK, em, o));
                Rest = em;
            }
            float Ee = (lane == 0) ? 0.0f : ex2(fminf(e - Rest, 122.0f));
            float ss = Ee;                        // prefix sum of exps
#pragma unroll
            for (int o = 1; o < 32; o <<= 1) {
                float tS = __shfl_up_sync(FULLMASK, ss, o);
                if (lane >= o) ss += tS;
            }
            float bseP = Rest + lg2(ss + FLR);
            float bse = (lane == 0) ? NEG2 : bseP;
            Rest = __shfl_sync(FULLMASK, bseP, 31);   // track for next row

            // ---------- LATE (needs mailbox slot i) ----------
            float hm = NEG2, hx = NEG2, hy = NEG2;
            if (s > 0) {
                waitflag(&ff[s - 1][i]);
                hm = fm[s - 1][i]; hx = fx[s - 1][i]; hy = fy[s - 1][i];
            }
            float q0  = lse2b(hm + A02, hx + A12);
            float aux = lse2b(q0 - A22, hy);          // t2b cancels exactly
            float y = S + lse2b(bse, aux);

            int wo = i * 384 + off;
            po[wo] = m; po[wo + 1] = x; po[wo + 2] = y;

            if (s < 3 && lane == 31) {
                fm[s][i] = m; fx[s][i] = x; fy[s][i] = y;
                relstore(&ff[s][i], 1);
            }
            if (i == 127) { la0 = m; la1 = x; la2 = y; }

            pm = m; px = x; py = y;
            dM = hm; dX = hx; dY = hy;
            if (i < 127) { t0 = n0 * INVLN2; t1 = n1 * INVLN2; t2 = n2 * INVLN2; }
        }
        if (s == 3) {   // logZ (base-2) from alpha(127,127,:) held in lane 31
            la0 = __shfl_sync(FULLMASK, la0, 31);
            la1 = __shfl_sync(FULLMASK, la1, 31);
            la2 = __shfl_sync(FULLMASK, la2, 31);
            float r = fmax3(la0, la1, la2);
            float lz = r + lg2(ex2(la0 - r) + ex2(la1 - r) + ex2(la2 - r));
            if (lane == 31) shlogZ = lz;
        }
    } else {
        // ====================== BETA (independent lattice, base-2) ==========
        const int wl = w - 4;                 // 0..3
        const int v = 3 - wl;                 // v=0 is the rightmost (producer) seg
        const int col = 32 * wl + 31 - lane;  // scan pos p = 32v+lane -> col 127-p
        const int off = col * 3;
        float u0p = NEG2, u1p = NEG2;
        float u0ext = NEG2;                   // bu0s[v-1][i+1], carried in a reg
        float Rest = BIGNEG;

        float t0 = th[127 * 384 + off] * INVLN2;
        float t1 = th[127 * 384 + off + 1] * INVLN2;
        float t2 = th[127 * 384 + off + 2] * INVLN2;
        for (int i = 127; i >= 0; i--) {
            float n0, n1, n2;
            if (i > 0) {
                int r = (i - 1) * 384 + off;
                n0 = th[r]; n1 = th[r + 1]; n2 = th[r + 2];
            }

            const bool lastcell = (v == 0 && lane == 0 && i == 127);

            // ---- S prefix-sum (theta-only) ----
            float d = t2 + A22;
            if (lastcell) d = 0.0f;
            float S = d;
#pragma unroll
            for (int o = 1; o < 32; o <<= 1) {
                float tS = __shfl_up_sync(FULLMASK, S, o);
                if (lane >= o) S += tS;
            }

            float u0n = __shfl_up_sync(FULLMASK, u0p, 1);
            if (lane == 0) u0n = u0ext;       // v==0: stays NEG2

            float c = t2 + lse2b(A20 + u0n, A21 + u1p);
            if (lastcell) c = t2;             // beta(127,127)=0

            float e = c - S;
            if (Rest < -1.0e8f) {             // cold segment: exact max
                float em = e;
#pragma unroll
                for (int o = 16; o > 0; o >>= 1)
                    em = fmaxf(em, __shfl_xor_sync(FULLMASK, em, o));
                Rest = em;
            }
            float Ee = ex2(fminf(e - Rest, 122.0f));
            float ss = Ee;
#pragma unroll
            for (int o = 1; o < 32; o <<= 1) {
                float tS = __shfl_up_sync(FULLMASK, ss, o);
                if (lane >= o) ss += tS;
            }
            float bse = Rest + lg2(ss + FLR);
            Rest = __shfl_sync(FULLMASK, bse, 31);

            // ---------- LATE ----------
            float seed = NEG2, nexu0 = NEG2;
            if (v > 0) {
                waitflag(&bf[v - 1][i]);
                seed  = bu2s[v - 1][i];
                nexu0 = bu0s[v - 1][i];       // becomes u0ext for row i-1
            }
            float y = S + lse2b(bse, seed);   // inclusive u2 at this column
            float wr = __shfl_up_sync(FULLMASK, y, 1);
            if (lane == 0) wr = seed;         // exclusive (u2 at col j+1)

            float rr = fmax3(u0n, u1p, wr);
            float e0 = ex2(u0n - rr), e1 = ex2(u1p - rr), e2 = ex2(wr - rr);
            float bb0 = rr + lg2(fmaf(E[0], e0, fmaf(E[1], e1, fmaf(E[2], e2, FLR))));
            float bb1 = rr + lg2(fmaf(E[3], e0, fmaf(E[4], e1, fmaf(E[5], e2, FLR))));
            float bb2 = rr + lg2(fmaf(E[6], e0, fmaf(E[7], e1, fmaf(E[8], e2, FLR))));
            if (lastcell) { bb0 = 0.f; bb1 = 0.f; bb2 = 0.f; }

            int ro = i * 384 + off;
            pb[ro] = bb0; pb[ro + 1] = bb1; pb[ro + 2] = bb2;

            float nu0 = bb0 + t0;
            float nu1 = bb1 + t1;

            if (v < 3 && lane == 31) {
                bu0s[v][i] = nu0;
                bu2s[v][i] = y;
                relstore(&bf[v][i], 1);
            }
            u0p = nu0; u1p = nu1; u0ext = nexu0;
            if (i > 0) { t0 = n0 * INVLN2; t1 = n1 * INVLN2; t2 = n2 * INVLN2; }
        }
    }

    // ====================== COMBINE (convert back with *ln2) ================
    __syncthreads();
    const float lz = shlogZ;
    const float4* bp4 = reinterpret_cast<const float4*>(pb);
    float4* op4 = reinterpret_cast<float4*>(po);
#pragma unroll 4
    for (int t = tid; t < 12288; t += 256) {
        float4 a = op4[t];
        float4 bb = bp4[t];
        op4[t] = make_float4((a.x + bb.x - lz) * LN2, (a.y + bb.y - lz) * LN2,
                             (a.z + bb.z - lz) * LN2, (a.w + bb.w - lz) * LN2);
    }
}

extern "C" void kernel_launch(void* const* d_in, const int* in_sizes, int n_in,
                              void* d_out, int out_size)
{
    const float* theta = (const float*)d_in[0];
    const float* A     = (const float*)d_in[1];
    float* out         = (float*)d_out;
    int B = in_sizes[1] / 9;   // 256
    fb_kernel<<<B, 256>>>(theta, A, out);
}

// round 17
// speedup vs baseline: 1.6241x; 1.0210x over previous
#include <cuda_runtime.h>

#define FULLMASK 0xffffffffu
#define NEG2  (-1.4426950e9f)          // -1e9 in base-2 log domain
#define FLR   (1e-30f)
#define BIGNEG (-3.0e38f)
#define INVLN2 1.4426950408889634f
#define LN2    0.6931471805599453f

__device__ float g_beta[256 * 128 * 128 * 3];   // beta scratch (50.3 MB)

__device__ __forceinline__ float ex2(float x) {
    float r; asm("ex2.approx.ftz.f32 %0, %1;" : "=f"(r) : "f"(x)); return r;
}
__device__ __forceinline__ float lg2(float x) {
    float r; asm("lg2.approx.ftz.f32 %0, %1;" : "=f"(r) : "f"(x)); return r;
}
__device__ __forceinline__ float lse2b(float a, float b) {
    float mx = fmaxf(a, b);
    float mn = fminf(a, b);
    return mx + lg2(1.0f + ex2(mn - mx));
}
__device__ __forceinline__ float fmax3(float a, float b, float c) {
    return fmaxf(fmaxf(a, b), c);
}
__device__ __forceinline__ void relstore(int* p, int v) {
    asm volatile("st.release.cta.b32 [%0], %1;" :: "l"(p), "r"(v) : "memory");
}
__device__ __forceinline__ int acqload(int* p) {
    int v; asm volatile("ld.acquire.cta.b32 %0, [%1];" : "=r"(v) : "l"(p) : "memory");
    return v;
}
__device__ __forceinline__ void waitflag(int* p) {
    if (acqload(p)) return;
    int tries = 0;
    while (!acqload(p)) { if (++tries > 64) __nanosleep(64); }
}
// named-barrier rendezvous for one warp pair (64 threads)
__device__ __forceinline__ void barpair(int id) {
    asm volatile("bar.sync %0, 64;" :: "r"(id) : "memory");
}

// One CTA (16 warps) per batch. Pairs 0-3: forward alpha segments (cols
// 32s..32s+31, 1 col/lane); within a pair, warp q handles rows i%2==q,
// alternating through a named-barrier rendezvous with the row boundary
// (m,x,y) passed in smem. Pairs 4-7: beta lattice, same scheme descending
// rows. Cross-segment per-row mailboxes unchanged. Then coalesced combine.
__global__ void __launch_bounds__(512, 2)
fb_kernel(const float* __restrict__ theta, const float* __restrict__ Aall,
          float* __restrict__ out)
{
    __shared__ float fm[3][128], fx[3][128], fy[3][128];   // fwd mailboxes
    __shared__ int   ff[3][128];
    __shared__ float bu0s[3][128], bu2s[3][128];           // beta mailboxes
    __shared__ int   bf[3][128];
    __shared__ float hmT[4][2][32], hxT[4][2][32], hyT[4][2][32];  // fwd row handoff
    __shared__ float hb0[4][2][32], hb1[4][2][32];                 // beta row handoff
    __shared__ float shlogZ;

    const int tid  = threadIdx.x;
    const int w    = tid >> 5;
    const int lane = tid & 31;
    const int pair = w >> 1;
    const int q    = w & 1;
    const int b    = blockIdx.x;

    for (int j = tid; j < 3 * 128; j += 512) {
        (&ff[0][0])[j] = 0;
        (&bf[0][0])[j] = 0;
    }
    __syncthreads();

    const float* Ab = Aall + (size_t)b * 9;
    float As[9], E[9];
#pragma unroll
    for (int t = 0; t < 9; t++) { As[t] = Ab[t] * INVLN2; E[t] = ex2(As[t]); }
    const float A02 = As[2], A12 = As[5], A20 = As[6], A21 = As[7], A22 = As[8];
    const float eM0 = E[0], eM1 = E[3], eM2 = E[6];
    const float eX0 = E[1], eX1 = E[4], eX2 = E[7];

    const size_t base_off = (size_t)b * 49152;
    const float* th = theta + base_off;
    float* po = out + base_off;
    float* pb = g_beta + base_off;

    if (pair < 4) {
        // ====================== FORWARD (alpha, base-2) ======================
        const int s = pair;
        const int bid = 1 + pair;             // named barrier id
        const int col = s * 32 + lane;
        const int off = col * 3;
        float Rest = BIGNEG;
        float la0 = NEG2, la1 = NEG2, la2 = NEG2;

        for (int k = 0; k < 64; k++) {
            const int i = 2 * k + q;
            const int ro = i * 384 + off;
            // ---- pre-bar work: theta + S-scan + mailbox acquire ----
            float t0 = th[ro] * INVLN2, t1 = th[ro + 1] * INVLN2, t2 = th[ro + 2] * INVLN2;
            float S = t2 + A22;
#pragma unroll
            for (int o = 1; o < 32; o <<= 1) {
                float tS = __shfl_up_sync(FULLMASK, S, o);
                if (lane >= o) S += tS;
            }
            float hmv = NEG2, hxv = NEG2, hyv = NEG2;
            float dMv = NEG2, dXv = NEG2, dYv = NEG2;
            if (s > 0) {
                waitflag(&ff[s - 1][i]);
                hmv = fm[s - 1][i]; hxv = fx[s - 1][i]; hyv = fy[s - 1][i];
                if (i > 0) { dMv = fm[s - 1][i - 1]; dXv = fx[s - 1][i - 1]; dYv = fy[s - 1][i - 1]; }
            }
            // ---- rendezvous: partner's row i-1 boundary ----
            float pm, px, py;
            if (i == 0) { pm = NEG2; px = NEG2; py = NEG2; }
            else {
                barpair(bid);
                pm = hmT[s][q ^ 1][lane]; px = hxT[s][q ^ 1][lane]; py = hyT[s][q ^ 1][lane];
            }

            float r0 = fmax3(pm, px, py);
            float Em = ex2(pm - r0), Ex = ex2(px - r0), Ey = ex2(py - r0);
            float dotM = fmaf(eM0, Em, fmaf(eM1, Ex, fmaf(eM2, Ey, FLR)));
            float dotX = fmaf(eX0, Em, fmaf(eX1, Ex, fmaf(eX2, Ey, FLR)));
            float v = r0 + lg2(dotM);
            float x = t1 + r0 + lg2(dotX);

            float vsh = __shfl_up_sync(FULLMASK, v, 1);
            if (lane == 0) {
                if (s == 0) vsh = NEG2;
                else {
                    float rr = fmax3(dMv, dXv, dYv);
                    float a0 = ex2(dMv - rr), a1 = ex2(dXv - rr), a2 = ex2(dYv - rr);
                    vsh = rr + lg2(fmaf(eM0, a0, fmaf(eM1, a1, fmaf(eM2, a2, FLR))));
                }
                if (s == 0 && i == 0) vsh = 0.0f;    // start cell (0,0,match)
            }
            float m = t0 + vsh;

            float mnb = __shfl_up_sync(FULLMASK, m, 1);
            float xnb = __shfl_up_sync(FULLMASK, x, 1);
            float c = t2 + lse2b(mnb + A02, xnb + A12);   // lane0 garbage (excluded)

            float e = c - S;
            if (Rest < -1.0e8f) {
                float em = (lane == 0) ? BIGNEG : e;
#pragma unroll
                for (int o = 16; o > 0; o >>= 1)
                    em = fmaxf(em, __shfl_xor_sync(FULLMASK, em, o));
                Rest = em;
            }
            float Ee = (lane == 0) ? 0.0f : ex2(fminf(e - Rest, 122.0f));
            float ss = Ee;
#pragma unroll
            for (int o = 1; o < 32; o <<= 1) {
                float tS = __shfl_up_sync(FULLMASK, ss, o);
                if (lane >= o) ss += tS;
            }
            float bseP = Rest + lg2(ss + FLR);
            float bse = (lane == 0) ? NEG2 : bseP;
            Rest = __shfl_sync(FULLMASK, bseP, 31);

            float q0v = lse2b(hmv + A02, hxv + A12);
            float aux = lse2b(q0v - A22, hyv);
            float y = S + lse2b(bse, aux);

            po[ro] = m; po[ro + 1] = x; po[ro + 2] = y;

            if (s < 3 && lane == 31) {
                fm[s][i] = m; fx[s][i] = x; fy[s][i] = y;
                relstore(&ff[s][i], 1);
            }
            if (i == 127) { la0 = m; la1 = x; la2 = y; }

            if (!(q == 1 && k == 63)) {       // row 127 has no consumer
                hmT[s][q][lane] = m; hxT[s][q][lane] = x; hyT[s][q][lane] = y;
                barpair(bid);
            }
        }
        if (s == 3 && q == 1) {   // logZ (base-2) from alpha(127,127,:) in lane 31
            la0 = __shfl_sync(FULLMASK, la0, 31);
            la1 = __shfl_sync(FULLMASK, la1, 31);
            la2 = __shfl_sync(FULLMASK, la2, 31);
            float r = fmax3(la0, la1, la2);
            float lz = r + lg2(ex2(la0 - r) + ex2(la1 - r) + ex2(la2 - r));
            if (lane == 31) shlogZ = lz;
        }
    } else {
        // ====================== BETA (independent lattice, base-2) ==========
        const int wl = pair - 4;              // 0..3
        const int vv = 3 - wl;                // vv=0 is the rightmost (producer) seg
        const int bid = 1 + pair;             // ids 5..8
        const int col = 32 * wl + 31 - lane;  // scan pos p = 32vv+lane -> col 127-p
        const int off = col * 3;
        float Rest = BIGNEG;

        for (int k = 0; k < 64; k++) {
            const int i = 127 - 2 * k - q;
            const int ro = i * 384 + off;
            const bool lastcell = (vv == 0 && lane == 0 && i == 127);

            // ---- pre-bar work ----
            float t0 = th[ro] * INVLN2, t1 = th[ro + 1] * INVLN2, t2 = th[ro + 2] * INVLN2;
            float dd = t2 + A22;
            if (lastcell) dd = 0.0f;
            float S = dd;
#pragma unroll
            for (int o = 1; o < 32; o <<= 1) {
                float tS = __shfl_up_sync(FULLMASK, S, o);
                if (lane >= o) S += tS;
            }
            float seed = NEG2, u0e = NEG2;
            if (vv > 0) {
                waitflag(&bf[vv - 1][i]);
                seed = bu2s[vv - 1][i];
                if (i < 127) u0e = bu0s[vv - 1][i + 1];
            }
            // ---- rendezvous: partner's row i+1 (nu0, nu1) ----
            float u0p_, u1p_;
            if (i == 127) { u0p_ = NEG2; u1p_ = NEG2; }
            else {
                barpair(bid);
                u0p_ = hb0[wl][q ^ 1][lane]; u1p_ = hb1[wl][q ^ 1][lane];
            }

            float u0n = __shfl_up_sync(FULLMASK, u0p_, 1);
            if (lane == 0) u0n = u0e;

            float c = t2 + lse2b(A20 + u0n, A21 + u1p_);
            if (lastcell) c = t2;             // beta(127,127)=0

            float e = c - S;
            if (Rest < -1.0e8f) {
                float em = e;
#pragma unroll
                for (int o = 16; o > 0; o >>= 1)
                    em = fmaxf(em, __shfl_xor_sync(FULLMASK, em, o));
                Rest = em;
            }
            float Ee = ex2(fminf(e - Rest, 122.0f));
            float ss = Ee;
#pragma unroll
            for (int o = 1; o < 32; o <<= 1) {
                float tS = __shfl_up_sync(FULLMASK, ss, o);
                if (lane >= o) ss += tS;
            }
            float bse = Rest + lg2(ss + FLR);
            Rest = __shfl_sync(FULLMASK, bse, 31);

            float y = S + lse2b(bse, seed);   // inclusive u2 at this column
            float wr = __shfl_up_sync(FULLMASK, y, 1);
            if (lane == 0) wr = seed;         // exclusive (u2 at col j+1)

            float rr = fmax3(u0n, u1p_, wr);
            float e0 = ex2(u0n - rr), e1 = ex2(u1p_ - rr), e2 = ex2(wr - rr);
            float bb0 = rr + lg2(fmaf(E[0], e0, fmaf(E[1], e1, fmaf(E[2], e2, FLR))));
            float bb1 = rr + lg2(fmaf(E[3], e0, fmaf(E[4], e1, fmaf(E[5], e2, FLR))));
            float bb2 = rr + lg2(fmaf(E[6], e0, fmaf(E[7], e1, fmaf(E[8], e2, FLR))));
            if (lastcell) { bb0 = 0.f; bb1 = 0.f; bb2 = 0.f; }

            pb[ro] = bb0; pb[ro + 1] = bb1; pb[ro + 2] = bb2;

            float nu0 = bb0 + t0;
            float nu1 = bb1 + t1;

            if (vv < 3 && lane == 31) {
                bu0s[vv][i] = nu0;
                bu2s[vv][i] = y;
                relstore(&bf[vv][i], 1);
            }
            if (!(q == 1 && k == 63)) {       // row 0 has no consumer
                hb0[wl][q][lane] = nu0; hb1[wl][q][lane] = nu1;
                barpair(bid);
            }
        }
    }

    // ====================== COMBINE (convert back with *ln2) ================
    __syncthreads();
    const float lz = shlogZ;
    const float4* bp4 = reinterpret_cast<const float4*>(pb);
    float4* op4 = reinterpret_cast<float4*>(po);
#pragma unroll 4
    for (int t = tid; t < 12288; t += 512) {
        float4 a = op4[t];
        float4 bb = bp4[t];
        op4[t] = make_float4((a.x + bb.x - lz) * LN2, (a.y + bb.y - lz) * LN2,
                             (a.z + bb.z - lz) * LN2, (a.w + bb.w - lz) * LN2);
    }
}

extern "C" void kernel_launch(void* const* d_in, const int* in_sizes, int n_in,
                              void* d_out, int out_size)
{
    const float* theta = (const float*)d_in[0];
    const float* A     = (const float*)d_in[1];
    float* out         = (float*)d_out;
    int B = in_sizes[1] / 9;   // 256
    fb_kernel<<<B, 512>>>(theta, A, out);
}